// round 7
// baseline (speedup 1.0000x reference)
#include <cuda_runtime.h>
#include <math.h>

#define NF     256
#define TOPK   32
#define WIN    128
#define EMB    128
#define BATCH  64
#define ALPHA  0.2f

// Scratch: Wx = x @ W + b, shape [BATCH*NF, EMB] = 8 MB (device global, no alloc)
__device__ float g_wx[BATCH * NF * EMB];

// ---------------------------------------------------------------------------
// Kernel 1: Wx[r][e] = sum_w x[r][w] * W[w][e] + b[e]
// M=16384, N=128, K=128. BM=32 (grid 512), BK=16; A and B tiles both
// double-buffered -> one __syncthreads per K-step. 256 threads, 2x8 micro-tile.
// ---------------------------------------------------------------------------
__global__ __launch_bounds__(256) void gemm_kernel(const float* __restrict__ x,
                                                   const float* __restrict__ W,
                                                   const float* __restrict__ bias) {
    __shared__ float As[2][32][17];    // padded
    __shared__ float Bs[2][16][128];

    const int tid  = threadIdx.x;
    const int row0 = blockIdx.x * 32;
    const int ty   = tid >> 4;         // 0..15 -> rows {2ty, 2ty+1}
    const int tx   = tid & 15;         // 0..15 -> cols tx*8..tx*8+7

    // A loader: 32x16 = 512 floats, one float2 per thread
    const int ar = tid >> 3;           // 0..31
    const int ak = (tid & 7) << 1;     // 0,2,..,14
    const float* xrow = x + (size_t)(row0 + ar) * 128 + ak;

    // B loader: 16x128 = 512 float4, two per thread
    const int bk0 = (tid) >> 5,        bc0 = (tid & 31) << 2;
    const int bk1 = (tid + 256) >> 5,  bc1 = bc0;

    // Preload kc=0
    {
        float2 av = *(const float2*)(xrow);
        As[0][ar][ak] = av.x; As[0][ar][ak + 1] = av.y;
        *(float4*)(&Bs[0][bk0][bc0]) = *(const float4*)(W + (size_t)bk0 * 128 + bc0);
        *(float4*)(&Bs[0][bk1][bc1]) = *(const float4*)(W + (size_t)bk1 * 128 + bc1);
    }
    __syncthreads();

    float acc[2][8];
#pragma unroll
    for (int i = 0; i < 2; i++)
#pragma unroll
        for (int j = 0; j < 8; j++) acc[i][j] = 0.f;

#pragma unroll
    for (int kc = 0; kc < 8; kc++) {
        const int cur = kc & 1;
        float2 na;
        float4 nb0, nb1;
        if (kc < 7) {
            na  = *(const float2*)(xrow + (kc + 1) * 16);
            nb0 = *(const float4*)(W + (size_t)((kc + 1) * 16 + bk0) * 128 + bc0);
            nb1 = *(const float4*)(W + (size_t)((kc + 1) * 16 + bk1) * 128 + bc1);
        }

#pragma unroll
        for (int k = 0; k < 16; k++) {
            float a0 = As[cur][ty * 2 + 0][k];
            float a1 = As[cur][ty * 2 + 1][k];
            float4 b0 = *(float4*)(&Bs[cur][k][tx * 8]);
            float4 b1 = *(float4*)(&Bs[cur][k][tx * 8 + 4]);
            float bb[8] = {b0.x, b0.y, b0.z, b0.w, b1.x, b1.y, b1.z, b1.w};
#pragma unroll
            for (int j = 0; j < 8; j++) {
                acc[0][j] = fmaf(a0, bb[j], acc[0][j]);
                acc[1][j] = fmaf(a1, bb[j], acc[1][j]);
            }
        }

        if (kc < 7) {
            const int nxt = cur ^ 1;
            As[nxt][ar][ak] = na.x; As[nxt][ar][ak + 1] = na.y;
            *(float4*)(&Bs[nxt][bk0][bc0]) = nb0;
            *(float4*)(&Bs[nxt][bk1][bc1]) = nb1;
            __syncthreads();
        }
    }

#pragma unroll
    for (int i = 0; i < 2; i++) {
        int row = row0 + ty * 2 + i;
#pragma unroll
        for (int j = 0; j < 8; j += 4) {
            float4 v;
            v.x = acc[i][j + 0] + bias[tx * 8 + j + 0];
            v.y = acc[i][j + 1] + bias[tx * 8 + j + 1];
            v.z = acc[i][j + 2] + bias[tx * 8 + j + 2];
            v.w = acc[i][j + 3] + bias[tx * 8 + j + 3];
            *(float4*)(g_wx + (size_t)row * 128 + tx * 8 + j) = v;
        }
    }
}

// ---------------------------------------------------------------------------
// Kernel 2: one CTA per (b, n). Register-resident rows, ONE barrier.
// Parity trick: e[k>=16] = p[2(k-16)] + q[2(k-16)+1] -> even rows only ever
// need dot(row, a1), odd rows only dot(row, a2). Warp w's rows {w,w+8,w+16,w+24}
// share parity w&1 -> one dot per row with the warp's a-half.
// Self row (k<16 logits): dot(self, a1+a2), computed by warp 0.
// Softmax is recomputed redundantly by every warp (lane = k) -> no second
// barrier, no idle warps. Output streamed from registers with __stcs.
// ---------------------------------------------------------------------------
__global__ __launch_bounds__(256, 6) void attn_kernel(const int*   __restrict__ edges,
                                                      const float* __restrict__ avec,
                                                      const float* __restrict__ bias_n,
                                                      float*       __restrict__ out) {
    __shared__ float s[33];   // s[j] = parity-dot of row j; s[32] = dot(self, a1+a2)

    const int bn   = blockIdx.x;
    const int b    = bn >> 8;
    const int n    = bn & 255;
    const int tid  = threadIdx.x;
    const int wid  = tid >> 5;
    const int lane = tid & 31;

    // This warp's a-half (a1 for even warps/rows, a2 for odd)
    const float4 av = (wid & 1)
        ? *(const float4*)(avec + 128 + lane * 4)
        : *(const float4*)(avec + lane * 4);

    // Gather this warp's 4 rows and compute parity dots
    float4 vrow[4];
    float  d[4];
#pragma unroll
    for (int i = 0; i < 4; i++) {
        const int j  = wid + i * 8;
        const int nb = __ldg(edges + n * 32 + j);
        const float4 v = *(const float4*)(g_wx + (size_t)(b * NF + nb) * 128 + lane * 4);
        vrow[i] = v;
        d[i] = v.x * av.x + v.y * av.y + v.z * av.z + v.w * av.w;
    }

    // Interleaved xor-butterfly reductions (all lanes end with the sum)
#pragma unroll
    for (int o = 16; o; o >>= 1) {
#pragma unroll
        for (int i = 0; i < 4; i++)
            d[i] += __shfl_xor_sync(0xffffffffu, d[i], o);
    }
    if (lane == 0) {
#pragma unroll
        for (int i = 0; i < 4; i++) s[wid + i * 8] = d[i];
    }

    if (wid == 0) {  // self row logit: dot(self, a1 + a2)
        const float4 a2 = *(const float4*)(avec + 128 + lane * 4);
        const float4 v  = *(const float4*)(g_wx + (size_t)bn * 128 + lane * 4);
        float ds = v.x * (av.x + a2.x) + v.y * (av.y + a2.y)
                 + v.z * (av.z + a2.z) + v.w * (av.w + a2.w);
#pragma unroll
        for (int o = 16; o; o >>= 1) ds += __shfl_xor_sync(0xffffffffu, ds, o);
        if (lane == 0) s[32] = ds;
    }
    __syncthreads();

    // Softmax, redundantly per warp: lane = k
    float att_lane;
    {
        const int k = lane;
        float raw = (k < 16) ? s[32] : s[2 * (k - 16)] + s[2 * (k - 16) + 1];
        float e = raw > 0.f ? raw : ALPHA * raw;
        float bz = __ldg(bias_n + n * 32 + k);
        if (isnan(bz))       bz = 0.f;
        else if (isinf(bz))  bz = bz > 0.f ? 3.402823466e38f : -3.402823466e38f;
        e += bz;
        float mx = e;
#pragma unroll
        for (int o = 16; o; o >>= 1) mx = fmaxf(mx, __shfl_xor_sync(0xffffffffu, mx, o));
        float ex = __expf(e - mx);   // arg <= 0, moderate range
        float sm = ex;
#pragma unroll
        for (int o = 16; o; o >>= 1) sm += __shfl_xor_sync(0xffffffffu, sm, o);
        att_lane = ex / sm;
    }

    // Output from registers: warp w writes rows {w, w+8, w+16, w+24}
    float* outb = out + (size_t)bn * (TOPK * EMB);
#pragma unroll
    for (int i = 0; i < 4; i++) {
        const int j = wid + i * 8;
        const float att = __shfl_sync(0xffffffffu, att_lane, j);
        float4 v = vrow[i];
        v.x *= att; v.y *= att; v.z *= att; v.w *= att;
        v.x = v.x > 0.f ? v.x : ALPHA * v.x;
        v.y = v.y > 0.f ? v.y : ALPHA * v.y;
        v.z = v.z > 0.f ? v.z : ALPHA * v.z;
        v.w = v.w > 0.f ? v.w : ALPHA * v.w;
        __stcs((float4*)(outb + j * 128 + lane * 4), v);  // streaming store
    }
}

// ---------------------------------------------------------------------------
// Inputs (metadata order): x_n, x_e(unused), edge_indices, all_embeddings(unused),
//                          W_n, b_n, a, bias_n. Output: float32 [B,NF,K,E].
// ---------------------------------------------------------------------------
extern "C" void kernel_launch(void* const* d_in, const int* in_sizes, int n_in,
                              void* d_out, int out_size) {
    const float* x      = (const float*)d_in[0];
    const int*   edges  = (const int*)  d_in[2];
    const float* W      = (const float*)d_in[4];
    const float* bvec   = (const float*)d_in[5];
    const float* a      = (const float*)d_in[6];
    const float* biasn  = (const float*)d_in[7];
    float*       out    = (float*)d_out;

    gemm_kernel<<<(BATCH * NF) / 32, 256>>>(x, W, bvec);
    attn_kernel<<<BATCH * NF, 256>>>(edges, a, biasn, out);
}

// round 8
// speedup vs baseline: 1.1586x; 1.1586x over previous
#include <cuda_runtime.h>
#include <math.h>

#define NF     256
#define TOPK   32
#define WIN    128
#define EMB    128
#define BATCH  64
#define ALPHA  0.2f

// Scratch: Wx = x @ W + b, shape [BATCH*NF, EMB] = 8 MB (device global, no alloc)
__device__ float g_wx[BATCH * NF * EMB];

// ---------------------------------------------------------------------------
// Kernel 1 (reverted to R6 — measured 22.6us): Wx[r][e] = sum_w x[r][w]*W[w][e]+b[e]
// M=16384, N=128, K=128. BM=64; W (128x128, 64KB) fully SMEM-resident;
// A tiles (64x16) double-buffered -> ONE __syncthreads per K-step.
// 256 threads; 4x8 micro-tile per thread.
// ---------------------------------------------------------------------------
__global__ __launch_bounds__(256) void gemm_kernel(const float* __restrict__ x,
                                                   const float* __restrict__ W,
                                                   const float* __restrict__ bias) {
    __shared__ float Ws[128][128];     // full W, 64 KB
    __shared__ float As[2][64][17];    // double-buffered A tile, padded

    const int tid  = threadIdx.x;
    const int row0 = blockIdx.x * 64;
    const int ty   = tid >> 4;         // 0..15 -> rows ty*4..ty*4+3
    const int tx   = tid & 15;         // 0..15 -> cols tx*8..tx*8+7

    // Load full W: 4096 float4, 16 per thread (coalesced)
#pragma unroll
    for (int i = 0; i < 16; i++) {
        int idx = tid + i * 256;
        int kr  = idx >> 5;
        int cc  = (idx & 31) << 2;
        *(float4*)(&Ws[kr][cc]) = *(const float4*)(W + (size_t)kr * 128 + cc);
    }

    // A loader mapping: thread -> (row ar, k-chunk ak)
    const int ar = tid >> 2;           // 0..63
    const int ak = (tid & 3) << 2;     // 0,4,8,12
    const float* xrow = x + (size_t)(row0 + ar) * 128 + ak;

    // Preload first A tile into buffer 0
    {
        float4 av = *(const float4*)(xrow);
        As[0][ar][ak + 0] = av.x; As[0][ar][ak + 1] = av.y;
        As[0][ar][ak + 2] = av.z; As[0][ar][ak + 3] = av.w;
    }
    __syncthreads();

    float acc[4][8];
#pragma unroll
    for (int i = 0; i < 4; i++)
#pragma unroll
        for (int j = 0; j < 8; j++) acc[i][j] = 0.f;

#pragma unroll
    for (int kc = 0; kc < 8; kc++) {
        const int cur = kc & 1;
        float4 nxt;
        if (kc < 7) nxt = *(const float4*)(xrow + (kc + 1) * 16);

#pragma unroll
        for (int k = 0; k < 16; k++) {
            float a[4];
#pragma unroll
            for (int i = 0; i < 4; i++) a[i] = As[cur][ty * 4 + i][k];
            float4 b0 = *(float4*)(&Ws[kc * 16 + k][tx * 8]);
            float4 b1 = *(float4*)(&Ws[kc * 16 + k][tx * 8 + 4]);
            float bb[8] = {b0.x, b0.y, b0.z, b0.w, b1.x, b1.y, b1.z, b1.w};
#pragma unroll
            for (int i = 0; i < 4; i++)
#pragma unroll
                for (int j = 0; j < 8; j++)
                    acc[i][j] = fmaf(a[i], bb[j], acc[i][j]);
        }

        if (kc < 7) {
            As[cur ^ 1][ar][ak + 0] = nxt.x; As[cur ^ 1][ar][ak + 1] = nxt.y;
            As[cur ^ 1][ar][ak + 2] = nxt.z; As[cur ^ 1][ar][ak + 3] = nxt.w;
            __syncthreads();
        }
    }

#pragma unroll
    for (int i = 0; i < 4; i++) {
        int row = row0 + ty * 4 + i;
#pragma unroll
        for (int j = 0; j < 8; j += 4) {
            float4 v;
            v.x = acc[i][j + 0] + bias[tx * 8 + j + 0];
            v.y = acc[i][j + 1] + bias[tx * 8 + j + 1];
            v.z = acc[i][j + 2] + bias[tx * 8 + j + 2];
            v.w = acc[i][j + 3] + bias[tx * 8 + j + 3];
            *(float4*)(g_wx + (size_t)row * 128 + tx * 8 + j) = v;
        }
    }
}

// ---------------------------------------------------------------------------
// Kernel 2: one CTA per (b-pair, n) — TWO batches share one neighbor list,
// one barrier, one softmax-logit setup. Register-resident rows (8 per warp).
// Parity trick: e[k>=16] = p[2(k-16)] + q[2(k-16)+1]: even rows only need
// dot(.,a1), odd rows only dot(.,a2); warp w's rows {w,w+8,w+16,w+24} share
// parity w&1. Self rows need dot(self, a1+a2) (warp 0, both batches).
// Softmax recomputed redundantly per warp (lane = k). __stcs streaming stores.
// ---------------------------------------------------------------------------
__global__ __launch_bounds__(256, 4) void attn_kernel(const int*   __restrict__ edges,
                                                      const float* __restrict__ avec,
                                                      const float* __restrict__ bias_n,
                                                      float*       __restrict__ out) {
    __shared__ float s0[33], s1[33];

    const int bn   = blockIdx.x;          // 0..8191
    const int n    = bn & 255;
    const int bp   = bn >> 8;             // batch pair 0..31
    const int b0   = bp * 2;
    const int b1   = b0 + 1;
    const int tid  = threadIdx.x;
    const int wid  = tid >> 5;
    const int lane = tid & 31;

    // This warp's a-half (a1 for even rows, a2 for odd rows)
    const float4 av = (wid & 1)
        ? *(const float4*)(avec + 128 + lane * 4)
        : *(const float4*)(avec + lane * 4);

    // Gather this warp's 4 rows for both batches; parity dots
    float4 v0[4], v1[4];
    float  d0[4], d1[4];
#pragma unroll
    for (int i = 0; i < 4; i++) {
        const int j  = wid + i * 8;
        const int nb = __ldg(edges + n * 32 + j);        // shared by both batches
        const float* r0 = g_wx + (size_t)(b0 * NF + nb) * 128 + lane * 4;
        const float* r1 = g_wx + (size_t)(b1 * NF + nb) * 128 + lane * 4;
        v0[i] = *(const float4*)r0;
        v1[i] = *(const float4*)r1;
        d0[i] = v0[i].x * av.x + v0[i].y * av.y + v0[i].z * av.z + v0[i].w * av.w;
        d1[i] = v1[i].x * av.x + v1[i].y * av.y + v1[i].z * av.z + v1[i].w * av.w;
    }

    // 8 interleaved xor-butterfly reductions
#pragma unroll
    for (int o = 16; o; o >>= 1) {
#pragma unroll
        for (int i = 0; i < 4; i++) {
            d0[i] += __shfl_xor_sync(0xffffffffu, d0[i], o);
            d1[i] += __shfl_xor_sync(0xffffffffu, d1[i], o);
        }
    }
    if (lane == 0) {
#pragma unroll
        for (int i = 0; i < 4; i++) {
            s0[wid + i * 8] = d0[i];
            s1[wid + i * 8] = d1[i];
        }
    }

    if (wid == 0) {  // self-row logits for both batches: dot(self, a1 + a2)
        const float4 a2 = *(const float4*)(avec + 128 + lane * 4);
        float4 asum; asum.x = av.x + a2.x; asum.y = av.y + a2.y;
                     asum.z = av.z + a2.z; asum.w = av.w + a2.w;
        const float4 vs0 = *(const float4*)(g_wx + (size_t)(b0 * NF + n) * 128 + lane * 4);
        const float4 vs1 = *(const float4*)(g_wx + (size_t)(b1 * NF + n) * 128 + lane * 4);
        float ds0 = vs0.x * asum.x + vs0.y * asum.y + vs0.z * asum.z + vs0.w * asum.w;
        float ds1 = vs1.x * asum.x + vs1.y * asum.y + vs1.z * asum.z + vs1.w * asum.w;
#pragma unroll
        for (int o = 16; o; o >>= 1) {
            ds0 += __shfl_xor_sync(0xffffffffu, ds0, o);
            ds1 += __shfl_xor_sync(0xffffffffu, ds1, o);
        }
        if (lane == 0) { s0[32] = ds0; s1[32] = ds1; }
    }
    __syncthreads();

    // Softmax for both batches, redundantly per warp: lane = k.
    // bias_n is batch-independent -> load once.
    float att0_lane, att1_lane;
    {
        const int k = lane;
        float bz = __ldg(bias_n + n * 32 + k);
        if (isnan(bz))       bz = 0.f;
        else if (isinf(bz))  bz = bz > 0.f ? 3.402823466e38f : -3.402823466e38f;

        float raw0 = (k < 16) ? s0[32] : s0[2 * (k - 16)] + s0[2 * (k - 16) + 1];
        float raw1 = (k < 16) ? s1[32] : s1[2 * (k - 16)] + s1[2 * (k - 16) + 1];
        float e0 = (raw0 > 0.f ? raw0 : ALPHA * raw0) + bz;
        float e1 = (raw1 > 0.f ? raw1 : ALPHA * raw1) + bz;

        float m0 = e0, m1 = e1;
#pragma unroll
        for (int o = 16; o; o >>= 1) {
            m0 = fmaxf(m0, __shfl_xor_sync(0xffffffffu, m0, o));
            m1 = fmaxf(m1, __shfl_xor_sync(0xffffffffu, m1, o));
        }
        float x0 = __expf(e0 - m0);   // arg <= 0, moderate range
        float x1 = __expf(e1 - m1);
        float t0 = x0, t1 = x1;
#pragma unroll
        for (int o = 16; o; o >>= 1) {
            t0 += __shfl_xor_sync(0xffffffffu, t0, o);
            t1 += __shfl_xor_sync(0xffffffffu, t1, o);
        }
        att0_lane = x0 / t0;
        att1_lane = x1 / t1;
    }

    // Output from registers: warp w writes rows {w, w+8, w+16, w+24} x 2 batches
    float* o0 = out + (size_t)(b0 * NF + n) * (TOPK * EMB);
    float* o1 = out + (size_t)(b1 * NF + n) * (TOPK * EMB);
#pragma unroll
    for (int i = 0; i < 4; i++) {
        const int j = wid + i * 8;
        const float a0 = __shfl_sync(0xffffffffu, att0_lane, j);
        const float a1 = __shfl_sync(0xffffffffu, att1_lane, j);
        float4 u = v0[i];
        u.x *= a0; u.y *= a0; u.z *= a0; u.w *= a0;
        u.x = u.x > 0.f ? u.x : ALPHA * u.x;
        u.y = u.y > 0.f ? u.y : ALPHA * u.y;
        u.z = u.z > 0.f ? u.z : ALPHA * u.z;
        u.w = u.w > 0.f ? u.w : ALPHA * u.w;
        __stcs((float4*)(o0 + j * 128 + lane * 4), u);

        float4 w4 = v1[i];
        w4.x *= a1; w4.y *= a1; w4.z *= a1; w4.w *= a1;
        w4.x = w4.x > 0.f ? w4.x : ALPHA * w4.x;
        w4.y = w4.y > 0.f ? w4.y : ALPHA * w4.y;
        w4.z = w4.z > 0.f ? w4.z : ALPHA * w4.z;
        w4.w = w4.w > 0.f ? w4.w : ALPHA * w4.w;
        __stcs((float4*)(o1 + j * 128 + lane * 4), w4);
    }
}

// ---------------------------------------------------------------------------
// Inputs (metadata order): x_n, x_e(unused), edge_indices, all_embeddings(unused),
//                          W_n, b_n, a, bias_n. Output: float32 [B,NF,K,E].
// ---------------------------------------------------------------------------
extern "C" void kernel_launch(void* const* d_in, const int* in_sizes, int n_in,
                              void* d_out, int out_size) {
    const float* x      = (const float*)d_in[0];
    const int*   edges  = (const int*)  d_in[2];
    const float* W      = (const float*)d_in[4];
    const float* bvec   = (const float*)d_in[5];
    const float* a      = (const float*)d_in[6];
    const float* biasn  = (const float*)d_in[7];
    float*       out    = (float*)d_out;

    gemm_kernel<<<(BATCH * NF) / 64, 256>>>(x, W, bvec);
    attn_kernel<<<(BATCH / 2) * NF, 256>>>(edges, a, biasn, out);
}